// round 3
// baseline (speedup 1.0000x reference)
#include <cuda_runtime.h>
#include <math.h>

#define BB    512
#define LL    100
#define MM    10
#define DD    256
#define NASP  14
#define BT    8
#define NPART 4          // pos-mean split factor
#define LCHUNK (LL/NPART) // 25

#define OFF_RS  0
#define OFF_ZS  (BB*DD)
#define OFF_ZN  (2*BB*DD)

__device__ float g_part[BB*NPART*DD];   // pos partial sums
__device__ float g_My[BB*DD];

// ---------------------------------------------------------------------------
// K1: pos partial means. grid = BB*NPART, 64 threads.
// block q of b covers rows [q*25, q*25+25). thread t = float4 column.
// ---------------------------------------------------------------------------
__global__ __launch_bounds__(64) void k_pospart(
    const int* __restrict__ pos, const float4* __restrict__ E4)
{
    __shared__ int idx[LCHUNK];
    const int t = threadIdx.x;
    const int b = blockIdx.x >> 2, q = blockIdx.x & 3;
    if (t < LCHUNK) idx[t] = pos[b * LL + q * LCHUNK + t];
    __syncthreads();

    float4 a0 = make_float4(0.f,0.f,0.f,0.f);
    float4 a1 = make_float4(0.f,0.f,0.f,0.f);
    #pragma unroll
    for (int l = 0; l < LCHUNK - 1; l += 2) {
        float4 v0 = E4[(size_t)idx[l]   * 64 + t];
        float4 v1 = E4[(size_t)idx[l+1] * 64 + t];
        a0.x += v0.x; a0.y += v0.y; a0.z += v0.z; a0.w += v0.w;
        a1.x += v1.x; a1.y += v1.y; a1.z += v1.z; a1.w += v1.w;
    }
    {   // l = 24
        float4 v = E4[(size_t)idx[LCHUNK-1] * 64 + t];
        a0.x += v.x; a0.y += v.y; a0.z += v.z; a0.w += v.w;
    }
    a0.x += a1.x; a0.y += a1.y; a0.z += a1.z; a0.w += a1.w;
    ((float4*)g_part)[blockIdx.x * 64 + t] = a0;
}

// ---------------------------------------------------------------------------
// K2: My[b] = M_w @ y_s[b] + M_b  (sums 4 partials, scales by 1/L)
// ---------------------------------------------------------------------------
__global__ __launch_bounds__(256) void k_my(
    const float* __restrict__ Mw, const float* __restrict__ Mb)
{
    __shared__ float ys[BT][DD];
    const int t = threadIdx.x;
    const int b0 = blockIdx.x * BT;
    #pragma unroll
    for (int i = 0; i < BT; i++) {
        const float* p = g_part + (size_t)(b0 + i) * NPART * DD + t;
        ys[i][t] = (p[0] + p[DD] + p[2*DD] + p[3*DD]) * (1.f/LL);
    }
    __syncthreads();

    const float* mr = Mw + t * DD;
    float acc[BT];
    #pragma unroll
    for (int i = 0; i < BT; i++) acc[i] = 0.f;
    #pragma unroll 4
    for (int d = 0; d < DD; d++) {
        float w = mr[d];
        #pragma unroll
        for (int i = 0; i < BT; i++) acc[i] += w * ys[i][d];
    }
    float bb = Mb[t];
    #pragma unroll
    for (int i = 0; i < BT; i++) g_My[(b0 + i) * DD + t] = acc[i] + bb;
}

// ---------------------------------------------------------------------------
// K3 fused, 64 threads/block:
//   blocks [0,BB):        attention -> z_s -> aspect head -> r_s
//   blocks [BB, BB+BB*MM): z_n = l2norm(sum_l e)  (mean cancels under l2norm)
// thread t owns float4 column t; no cross-phase reduction needed.
// ---------------------------------------------------------------------------
__global__ __launch_bounds__(64) void k_fused(
    const int* __restrict__ pos, const int* __restrict__ negs,
    const float4* __restrict__ E4,
    const float4* __restrict__ Tw4, const float4* __restrict__ lw4,
    const float* __restrict__ lb, float* __restrict__ out)
{
    __shared__ int idx[LL];
    __shared__ float sh2[2];
    const int t = threadIdx.x, blk = blockIdx.x;
    const int wid = t >> 5, lane = t & 31;

    if (blk >= BB) {
        // ------- negatives: z_n -------
        const int bm = blk - BB;
        if (t < 50) { idx[t] = negs[bm*LL + t]; idx[t+50] = negs[bm*LL + t + 50]; }
        __syncthreads();
        float4 a0 = make_float4(0.f,0.f,0.f,0.f);
        float4 a1 = make_float4(0.f,0.f,0.f,0.f);
        #pragma unroll 4
        for (int l = 0; l < LL; l += 2) {
            float4 v0 = E4[(size_t)idx[l]   * 64 + t];
            float4 v1 = E4[(size_t)idx[l+1] * 64 + t];
            a0.x += v0.x; a0.y += v0.y; a0.z += v0.z; a0.w += v0.w;
            a1.x += v1.x; a1.y += v1.y; a1.z += v1.z; a1.w += v1.w;
        }
        a0.x += a1.x; a0.y += a1.y; a0.z += a1.z; a0.w += a1.w;
        float ss = a0.x*a0.x + a0.y*a0.y + a0.z*a0.z + a0.w*a0.w;
        #pragma unroll
        for (int o = 16; o > 0; o >>= 1) ss += __shfl_xor_sync(0xffffffffu, ss, o);
        if (lane == 0) sh2[wid] = ss;
        __syncthreads();
        float inv = 1.f / fmaxf(sqrtf(sh2[0] + sh2[1]), 1e-12f);
        a0.x *= inv; a0.y *= inv; a0.z *= inv; a0.w *= inv;
        ((float4*)(out + OFF_ZN))[bm * 64 + t] = a0;
        return;
    }

    // ------- attention + aspect head -------
    __shared__ float4 Mys[64];
    __shared__ float wgt[LL];
    __shared__ float4 zs[64];
    __shared__ float lg[NASP];
    __shared__ float ps[NASP];
    const int b = blk;
    if (t < 50) { idx[t] = pos[b*LL + t]; idx[t+50] = pos[b*LL + t + 50]; }
    Mys[t] = ((const float4*)g_My)[b * 64 + t];
    __syncthreads();

    // per-token weights (warp per token, 2 warps)
    for (int l = wid; l < LL; l += 2) {
        const float4* er = E4 + (size_t)idx[l] * 64;
        float4 v1 = er[lane], v2 = er[lane + 32];
        float4 m1 = Mys[lane], m2 = Mys[lane + 32];
        float p = v1.x*m1.x + v1.y*m1.y + v1.z*m1.z + v1.w*m1.w
                + v2.x*m2.x + v2.y*m2.y + v2.z*m2.z + v2.w*m2.w;
        #pragma unroll
        for (int o = 16; o > 0; o >>= 1) p += __shfl_xor_sync(0xffffffffu, p, o);
        if (lane == 0) wgt[l] = expf(tanhf(p));
    }
    __syncthreads();

    // weighted sum (rows L1-hot from the dot pass); softmax denom cancels
    float4 a = make_float4(0.f,0.f,0.f,0.f);
    #pragma unroll 4
    for (int l = 0; l < LL; l++) {
        float w = wgt[l];
        float4 v = E4[(size_t)idx[l] * 64 + t];
        a.x += w*v.x; a.y += w*v.y; a.z += w*v.z; a.w += w*v.w;
    }
    float ss = a.x*a.x + a.y*a.y + a.z*a.z + a.w*a.w;
    #pragma unroll
    for (int o = 16; o > 0; o >>= 1) ss += __shfl_xor_sync(0xffffffffu, ss, o);
    if (lane == 0) sh2[wid] = ss;
    __syncthreads();
    {
        float inv = 1.f / fmaxf(sqrtf(sh2[0] + sh2[1]), 1e-12f);
        a.x *= inv; a.y *= inv; a.z *= inv; a.w *= inv;
        zs[t] = a;
        ((float4*)(out + OFF_ZS))[b * 64 + t] = a;
    }
    __syncthreads();

    // logits over 14 aspects (warp per aspect, 2 warps -> 7 each)
    for (int asp = wid; asp < NASP; asp += 2) {
        const float4* lr = lw4 + asp * 64;
        float4 v1 = lr[lane], v2 = lr[lane + 32];
        float4 z1 = zs[lane], z2 = zs[lane + 32];
        float p = v1.x*z1.x + v1.y*z1.y + v1.z*z1.z + v1.w*z1.w
                + v2.x*z2.x + v2.y*z2.y + v2.z*z2.z + v2.w*z2.w;
        #pragma unroll
        for (int o = 16; o > 0; o >>= 1) p += __shfl_xor_sync(0xffffffffu, p, o);
        if (lane == 0) lg[asp] = p + lb[asp];
    }
    __syncthreads();

    if (t == 0) {
        float mx = -1e30f;
        #pragma unroll
        for (int aa = 0; aa < NASP; aa++) mx = fmaxf(mx, lg[aa]);
        float s = 0.f;
        #pragma unroll
        for (int aa = 0; aa < NASP; aa++) { float e = expf(lg[aa]-mx); ps[aa] = e; s += e; }
        float inv = 1.f / s;
        #pragma unroll
        for (int aa = 0; aa < NASP; aa++) ps[aa] *= inv;
    }
    __syncthreads();

    float4 rr = make_float4(0.f,0.f,0.f,0.f);
    #pragma unroll
    for (int aa = 0; aa < NASP; aa++) {
        float p = ps[aa];
        float4 v = Tw4[aa * 64 + t];
        rr.x += p*v.x; rr.y += p*v.y; rr.z += p*v.z; rr.w += p*v.w;
    }
    float s2 = rr.x*rr.x + rr.y*rr.y + rr.z*rr.z + rr.w*rr.w;
    #pragma unroll
    for (int o = 16; o > 0; o >>= 1) s2 += __shfl_xor_sync(0xffffffffu, s2, o);
    if (lane == 0) sh2[wid] = s2;
    __syncthreads();
    {
        float inv = 1.f / fmaxf(sqrtf(sh2[0] + sh2[1]), 1e-12f);
        rr.x *= inv; rr.y *= inv; rr.z *= inv; rr.w *= inv;
        ((float4*)(out + OFF_RS))[b * 64 + t] = rr;
    }
}

extern "C" void kernel_launch(void* const* d_in, const int* in_sizes, int n_in,
                              void* d_out, int out_size)
{
    const int*   pos  = (const int*)d_in[0];
    const int*   negs = (const int*)d_in[1];
    const float* E_w  = (const float*)d_in[2];
    const float* T_w  = (const float*)d_in[3];
    const float* M_w  = (const float*)d_in[4];
    const float* M_b  = (const float*)d_in[5];
    const float* lw   = (const float*)d_in[6];
    const float* lb   = (const float*)d_in[7];
    float* out = (float*)d_out;

    k_pospart<<<BB * NPART, 64>>>(pos, (const float4*)E_w);
    k_my<<<BB / BT, DD>>>(M_w, M_b);
    k_fused<<<BB + BB * MM, 64>>>(pos, negs, (const float4*)E_w,
                                  (const float4*)T_w, (const float4*)lw,
                                  lb, out);
}

// round 4
// speedup vs baseline: 1.1081x; 1.1081x over previous
#include <cuda_runtime.h>
#include <math.h>

#define BB    512
#define LL    100
#define MM    10
#define DD    256
#define NASP  14
#define BT    4                 // batches per pos block
#define NPOSBLK (BB/BT)         // 128
#define NNEGBLK (BB*MM)         // 5120

#define OFF_RS  0
#define OFF_ZS  (BB*DD)
#define OFF_ZN  (2*BB*DD)

// ---------------------------------------------------------------------------
// Unified kernel, 256 threads/block.
//   blocks [0, NPOSBLK):  full pos chain for BT batches (mean -> My -> attn
//                         -> z_s -> aspect head -> r_s). Self-contained.
//   blocks [NPOSBLK, ..): z_n = l2norm(sum_l e)  (mean & global softmax denom
//                         cancel under l2norm).
// ---------------------------------------------------------------------------
__global__ __launch_bounds__(256) void k_all(
    const int* __restrict__ pos, const int* __restrict__ negs,
    const float4* __restrict__ E4,
    const float4* __restrict__ Mw4, const float* __restrict__ Mb,
    const float4* __restrict__ Tw4, const float4* __restrict__ lw4,
    const float* __restrict__ lb, float* __restrict__ out)
{
    __shared__ float4 red[256];
    __shared__ float sh8[8];
    const int t = threadIdx.x, blk = blockIdx.x;
    const int r = t >> 6, c = t & 63;          // gather phase / float4 col
    const int wid = t >> 5, lane = t & 31;

    if (blk >= NPOSBLK) {
        // ---------------- negatives: z_n ----------------
        __shared__ int idx[LL];
        const int bm = blk - NPOSBLK;
        if (t < LL) idx[t] = negs[bm * LL + t];
        __syncthreads();
        float4 a = make_float4(0.f,0.f,0.f,0.f);
        #pragma unroll 5
        for (int i = 0; i < LL / 4; i++) {
            float4 v = E4[(size_t)idx[i * 4 + r] * 64 + c];
            a.x += v.x; a.y += v.y; a.z += v.z; a.w += v.w;
        }
        red[t] = a;
        __syncthreads();
        if (t < 64) {
            float4 s = red[t], p1 = red[t+64], p2 = red[t+128], p3 = red[t+192];
            s.x += p1.x+p2.x+p3.x; s.y += p1.y+p2.y+p3.y;
            s.z += p1.z+p2.z+p3.z; s.w += p1.w+p2.w+p3.w;
            red[t] = s;
            float ss = s.x*s.x + s.y*s.y + s.z*s.z + s.w*s.w;
            #pragma unroll
            for (int o = 16; o > 0; o >>= 1) ss += __shfl_xor_sync(0xffffffffu, ss, o);
            if (lane == 0) sh8[wid] = ss;
        }
        __syncthreads();
        if (t < 64) {
            float inv = 1.f / fmaxf(sqrtf(sh8[0] + sh8[1]), 1e-12f);
            float4 s = red[t];
            s.x *= inv; s.y *= inv; s.z *= inv; s.w *= inv;
            ((float4*)(out + OFF_ZN))[bm * 64 + t] = s;
        }
        return;
    }

    // ---------------- pos chain for batches [b0, b0+BT) ----------------
    __shared__ int   idxs[BT][LL];
    __shared__ float ysm[BT][DD];
    __shared__ float Mys[BT][DD];
    __shared__ float wgt[LL];
    __shared__ float zs[DD];
    __shared__ float lg[NASP];
    __shared__ float ps[NASP];
    const int b0 = blk * BT;

    // load all indices
    for (int i = 0; i < BT; i++)
        if (t < LL) idxs[i][t] = pos[(b0 + i) * LL + t];
    __syncthreads();

    // Phase 1: means -> ysm[i][*]
    for (int i = 0; i < BT; i++) {
        float4 a = make_float4(0.f,0.f,0.f,0.f);
        #pragma unroll 5
        for (int j = 0; j < LL / 4; j++) {
            float4 v = E4[(size_t)idxs[i][j * 4 + r] * 64 + c];
            a.x += v.x; a.y += v.y; a.z += v.z; a.w += v.w;
        }
        red[t] = a;
        __syncthreads();
        if (t < 64) {
            float4 s = red[t], p1 = red[t+64], p2 = red[t+128], p3 = red[t+192];
            s.x = (s.x+p1.x+p2.x+p3.x) * (1.f/LL);
            s.y = (s.y+p1.y+p2.y+p3.y) * (1.f/LL);
            s.z = (s.z+p1.z+p2.z+p3.z) * (1.f/LL);
            s.w = (s.w+p1.w+p2.w+p3.w) * (1.f/LL);
            ((float4*)ysm[i])[t] = s;
        }
        __syncthreads();
    }

    // Phase 2: My[i][t] = Mw row t . ysm[i] + Mb[t]   (M_w read once for BT)
    {
        const float4* mr = Mw4 + t * 64;
        float acc[BT];
        #pragma unroll
        for (int i = 0; i < BT; i++) acc[i] = 0.f;
        #pragma unroll 4
        for (int d = 0; d < 64; d++) {
            float4 w = mr[d];
            #pragma unroll
            for (int i = 0; i < BT; i++) {
                acc[i] += w.x * ysm[i][4*d]   + w.y * ysm[i][4*d+1]
                        + w.z * ysm[i][4*d+2] + w.w * ysm[i][4*d+3];
            }
        }
        float bb = Mb[t];
        #pragma unroll
        for (int i = 0; i < BT; i++) Mys[i][t] = acc[i] + bb;
    }
    __syncthreads();

    // Phase 3: per-batch attention + aspect head
    for (int i = 0; i < BT; i++) {
        const int b = b0 + i;

        // token weights: w_l = exp(tanh(e_l . My))  (warp per token)
        for (int l = wid; l < LL; l += 8) {
            const float4* er = E4 + (size_t)idxs[i][l] * 64;
            float4 v1 = er[lane], v2 = er[lane + 32];
            float p = v1.x * Mys[i][4*lane+0] + v1.y * Mys[i][4*lane+1]
                    + v1.z * Mys[i][4*lane+2] + v1.w * Mys[i][4*lane+3]
                    + v2.x * Mys[i][128+4*lane+0] + v2.y * Mys[i][128+4*lane+1]
                    + v2.z * Mys[i][128+4*lane+2] + v2.w * Mys[i][128+4*lane+3];
            #pragma unroll
            for (int o = 16; o > 0; o >>= 1) p += __shfl_xor_sync(0xffffffffu, p, o);
            if (lane == 0) wgt[l] = expf(tanhf(p));
        }
        __syncthreads();

        // weighted sum (rows L1-hot from the dot pass); denom cancels
        float4 a = make_float4(0.f,0.f,0.f,0.f);
        #pragma unroll 5
        for (int j = 0; j < LL / 4; j++) {
            const int l = j * 4 + r;
            const float w = wgt[l];
            float4 v = E4[(size_t)idxs[i][l] * 64 + c];
            a.x += w*v.x; a.y += w*v.y; a.z += w*v.z; a.w += w*v.w;
        }
        red[t] = a;
        __syncthreads();
        if (t < 64) {
            float4 s = red[t], p1 = red[t+64], p2 = red[t+128], p3 = red[t+192];
            s.x += p1.x+p2.x+p3.x; s.y += p1.y+p2.y+p3.y;
            s.z += p1.z+p2.z+p3.z; s.w += p1.w+p2.w+p3.w;
            red[t] = s;
            float ss = s.x*s.x + s.y*s.y + s.z*s.z + s.w*s.w;
            #pragma unroll
            for (int o = 16; o > 0; o >>= 1) ss += __shfl_xor_sync(0xffffffffu, ss, o);
            if (lane == 0) sh8[wid] = ss;
        }
        __syncthreads();
        if (t < 64) {
            float inv = 1.f / fmaxf(sqrtf(sh8[0] + sh8[1]), 1e-12f);
            float4 s = red[t];
            s.x *= inv; s.y *= inv; s.z *= inv; s.w *= inv;
            ((float4*)zs)[t] = s;
            ((float4*)(out + OFF_ZS))[b * 64 + t] = s;
        }
        __syncthreads();

        // logits over 14 aspects (warp per aspect)
        for (int asp = wid; asp < NASP; asp += 8) {
            const float4* lr = lw4 + asp * 64;
            float4 v1 = lr[lane], v2 = lr[lane + 32];
            float p = v1.x * zs[4*lane+0] + v1.y * zs[4*lane+1]
                    + v1.z * zs[4*lane+2] + v1.w * zs[4*lane+3]
                    + v2.x * zs[128+4*lane+0] + v2.y * zs[128+4*lane+1]
                    + v2.z * zs[128+4*lane+2] + v2.w * zs[128+4*lane+3];
            #pragma unroll
            for (int o = 16; o > 0; o >>= 1) p += __shfl_xor_sync(0xffffffffu, p, o);
            if (lane == 0) lg[asp] = p + lb[asp];
        }
        __syncthreads();

        if (t == 0) {
            float mx = -1e30f;
            #pragma unroll
            for (int aa = 0; aa < NASP; aa++) mx = fmaxf(mx, lg[aa]);
            float s = 0.f;
            #pragma unroll
            for (int aa = 0; aa < NASP; aa++) { float e = expf(lg[aa]-mx); ps[aa] = e; s += e; }
            float inv = 1.f / s;
            #pragma unroll
            for (int aa = 0; aa < NASP; aa++) ps[aa] *= inv;
        }
        __syncthreads();

        {
            float rr = 0.f;
            #pragma unroll
            for (int aa = 0; aa < NASP; aa++) rr += ps[aa] * ((const float*)Tw4)[aa * DD + t];
            #pragma unroll
            for (int o = 16; o > 0; o >>= 1) rr += 0.f; // no-op keep structure
            // block l2norm over rr
            float v2 = rr * rr;
            #pragma unroll
            for (int o = 16; o > 0; o >>= 1) v2 += __shfl_xor_sync(0xffffffffu, v2, o);
            if (lane == 0) sh8[wid] = v2;
            __syncthreads();
            float tot = sh8[0]+sh8[1]+sh8[2]+sh8[3]+sh8[4]+sh8[5]+sh8[6]+sh8[7];
            float nrm = fmaxf(sqrtf(tot), 1e-12f);
            out[OFF_RS + b * DD + t] = rr / nrm;
        }
        __syncthreads();
    }
}

extern "C" void kernel_launch(void* const* d_in, const int* in_sizes, int n_in,
                              void* d_out, int out_size)
{
    const int*   pos  = (const int*)d_in[0];
    const int*   negs = (const int*)d_in[1];
    const float* E_w  = (const float*)d_in[2];
    const float* T_w  = (const float*)d_in[3];
    const float* M_w  = (const float*)d_in[4];
    const float* M_b  = (const float*)d_in[5];
    const float* lw   = (const float*)d_in[6];
    const float* lb   = (const float*)d_in[7];
    float* out = (float*)d_out;

    k_all<<<NPOSBLK + NNEGBLK, 256>>>(
        pos, negs, (const float4*)E_w,
        (const float4*)M_w, M_b,
        (const float4*)T_w, (const float4*)lw, lb, out);
}

// round 5
// speedup vs baseline: 1.2557x; 1.1332x over previous
#include <cuda_runtime.h>
#include <math.h>

#define BB    512
#define LL    100
#define MM    10
#define DD    256
#define NASP  14
#define BT    4
#define NPOSBLK (BB/BT)         // 128
#define NNEGBLK (BB*MM)         // 5120

#define OFF_RS  0
#define OFF_ZS  (BB*DD)
#define OFF_ZN  (2*BB*DD)

#define F4ADD(a, v) { a.x += v.x; a.y += v.y; a.z += v.z; a.w += v.w; }

// Gather-sum of 25 rows (l = 4*i + r, i in [0,25)) with 8-deep load batching.
__device__ __forceinline__ float4 gather25(
    const float4* __restrict__ E4, const int* __restrict__ idx,
    int r, int c)
{
    float4 a0 = make_float4(0.f,0.f,0.f,0.f);
    float4 a1 = make_float4(0.f,0.f,0.f,0.f);
    #pragma unroll
    for (int j = 0; j < 3; j++) {
        const int i0 = j * 8;
        float4 v0 = E4[(size_t)idx[(i0+0)*4+r] * 64 + c];
        float4 v1 = E4[(size_t)idx[(i0+1)*4+r] * 64 + c];
        float4 v2 = E4[(size_t)idx[(i0+2)*4+r] * 64 + c];
        float4 v3 = E4[(size_t)idx[(i0+3)*4+r] * 64 + c];
        float4 v4 = E4[(size_t)idx[(i0+4)*4+r] * 64 + c];
        float4 v5 = E4[(size_t)idx[(i0+5)*4+r] * 64 + c];
        float4 v6 = E4[(size_t)idx[(i0+6)*4+r] * 64 + c];
        float4 v7 = E4[(size_t)idx[(i0+7)*4+r] * 64 + c];
        F4ADD(a0, v0); F4ADD(a1, v1); F4ADD(a0, v2); F4ADD(a1, v3);
        F4ADD(a0, v4); F4ADD(a1, v5); F4ADD(a0, v6); F4ADD(a1, v7);
    }
    float4 v = E4[(size_t)idx[24*4+r] * 64 + c];
    F4ADD(a0, v);
    F4ADD(a0, a1);
    return a0;
}

// ---------------------------------------------------------------------------
// Unified kernel, 256 threads/block.
//   blocks [0, NPOSBLK):   full pos chain for BT batches (self-contained)
//   blocks [NPOSBLK, ...): z_n = l2norm(sum_l e)   (mean cancels under l2norm)
// ---------------------------------------------------------------------------
__global__ __launch_bounds__(256, 4) void k_all(
    const int* __restrict__ pos, const int* __restrict__ negs,
    const float4* __restrict__ E4,
    const float4* __restrict__ Mw4, const float* __restrict__ Mb,
    const float4* __restrict__ Tw4, const float4* __restrict__ lw4,
    const float* __restrict__ lb, float* __restrict__ out)
{
    __shared__ float4 red[256];
    __shared__ float sh8[8];
    const int t = threadIdx.x, blk = blockIdx.x;
    const int r = t >> 6, c = t & 63;
    const int wid = t >> 5, lane = t & 31;

    if (blk >= NPOSBLK) {
        // ---------------- negatives: z_n ----------------
        __shared__ int idx[LL];
        const int bm = blk - NPOSBLK;
        if (t < LL) idx[t] = negs[bm * LL + t];
        __syncthreads();

        float4 a = gather25(E4, idx, r, c);
        red[t] = a;
        __syncthreads();
        if (t < 64) {
            float4 s = red[t], p1 = red[t+64], p2 = red[t+128], p3 = red[t+192];
            s.x += p1.x+p2.x+p3.x; s.y += p1.y+p2.y+p3.y;
            s.z += p1.z+p2.z+p3.z; s.w += p1.w+p2.w+p3.w;
            red[t] = s;
            float ss = s.x*s.x + s.y*s.y + s.z*s.z + s.w*s.w;
            #pragma unroll
            for (int o = 16; o > 0; o >>= 1) ss += __shfl_xor_sync(0xffffffffu, ss, o);
            if (lane == 0) sh8[wid] = ss;
        }
        __syncthreads();
        if (t < 64) {
            float inv = 1.f / fmaxf(sqrtf(sh8[0] + sh8[1]), 1e-12f);
            float4 s = red[t];
            s.x *= inv; s.y *= inv; s.z *= inv; s.w *= inv;
            ((float4*)(out + OFF_ZN))[bm * 64 + t] = s;
        }
        return;
    }

    // ---------------- pos chain for batches [b0, b0+BT) ----------------
    __shared__ int   idxs[BT][LL];
    __shared__ float ysMy[BT][DD];     // ys in phase 1-2, then overlaid by My
    __shared__ float wgt[LL];
    __shared__ float zs[DD];
    __shared__ float lg[NASP];
    __shared__ float ps[NASP];
    const int b0 = blk * BT;

    for (int i = 0; i < BT; i++)
        if (t < LL) idxs[i][t] = pos[(b0 + i) * LL + t];
    __syncthreads();

    // Phase 1: means -> ysMy[i][*]
    for (int i = 0; i < BT; i++) {
        float4 a = gather25(E4, idxs[i], r, c);
        red[t] = a;
        __syncthreads();
        if (t < 64) {
            float4 s = red[t], p1 = red[t+64], p2 = red[t+128], p3 = red[t+192];
            s.x = (s.x+p1.x+p2.x+p3.x) * (1.f/LL);
            s.y = (s.y+p1.y+p2.y+p3.y) * (1.f/LL);
            s.z = (s.z+p1.z+p2.z+p3.z) * (1.f/LL);
            s.w = (s.w+p1.w+p2.w+p3.w) * (1.f/LL);
            ((float4*)ysMy[i])[t] = s;
        }
        __syncthreads();
    }

    // Phase 2: acc[i] = Mw row t . ys[i]; then overlay My into ysMy
    {
        const float4* mr = Mw4 + t * 64;
        float acc[BT];
        #pragma unroll
        for (int i = 0; i < BT; i++) acc[i] = 0.f;
        #pragma unroll 4
        for (int d = 0; d < 64; d++) {
            float4 w = mr[d];
            #pragma unroll
            for (int i = 0; i < BT; i++) {
                acc[i] += w.x * ysMy[i][4*d]   + w.y * ysMy[i][4*d+1]
                        + w.z * ysMy[i][4*d+2] + w.w * ysMy[i][4*d+3];
            }
        }
        float bb = Mb[t];
        __syncthreads();   // all reads of ys done before overwrite
        #pragma unroll
        for (int i = 0; i < BT; i++) ysMy[i][t] = acc[i] + bb;
    }
    __syncthreads();

    // Phase 3: per-batch attention + aspect head
    for (int i = 0; i < BT; i++) {
        const int b = b0 + i;

        for (int l = wid; l < LL; l += 8) {
            const float4* er = E4 + (size_t)idxs[i][l] * 64;
            float4 v1 = er[lane], v2 = er[lane + 32];
            float p = v1.x * ysMy[i][4*lane+0] + v1.y * ysMy[i][4*lane+1]
                    + v1.z * ysMy[i][4*lane+2] + v1.w * ysMy[i][4*lane+3]
                    + v2.x * ysMy[i][128+4*lane+0] + v2.y * ysMy[i][128+4*lane+1]
                    + v2.z * ysMy[i][128+4*lane+2] + v2.w * ysMy[i][128+4*lane+3];
            #pragma unroll
            for (int o = 16; o > 0; o >>= 1) p += __shfl_xor_sync(0xffffffffu, p, o);
            if (lane == 0) wgt[l] = expf(tanhf(p));
        }
        __syncthreads();

        // weighted sum (rows L1-hot from the dot pass); softmax denom cancels
        float4 a = make_float4(0.f,0.f,0.f,0.f);
        #pragma unroll 5
        for (int j = 0; j < LL / 4; j++) {
            const int l = j * 4 + r;
            const float w = wgt[l];
            float4 v = E4[(size_t)idxs[i][l] * 64 + c];
            a.x += w*v.x; a.y += w*v.y; a.z += w*v.z; a.w += w*v.w;
        }
        red[t] = a;
        __syncthreads();
        if (t < 64) {
            float4 s = red[t], p1 = red[t+64], p2 = red[t+128], p3 = red[t+192];
            s.x += p1.x+p2.x+p3.x; s.y += p1.y+p2.y+p3.y;
            s.z += p1.z+p2.z+p3.z; s.w += p1.w+p2.w+p3.w;
            red[t] = s;
            float ss = s.x*s.x + s.y*s.y + s.z*s.z + s.w*s.w;
            #pragma unroll
            for (int o = 16; o > 0; o >>= 1) ss += __shfl_xor_sync(0xffffffffu, ss, o);
            if (lane == 0) sh8[wid] = ss;
        }
        __syncthreads();
        if (t < 64) {
            float inv = 1.f / fmaxf(sqrtf(sh8[0] + sh8[1]), 1e-12f);
            float4 s = red[t];
            s.x *= inv; s.y *= inv; s.z *= inv; s.w *= inv;
            ((float4*)zs)[t] = s;
            ((float4*)(out + OFF_ZS))[b * 64 + t] = s;
        }
        __syncthreads();

        for (int asp = wid; asp < NASP; asp += 8) {
            const float4* lr = lw4 + asp * 64;
            float4 v1 = lr[lane], v2 = lr[lane + 32];
            float p = v1.x * zs[4*lane+0] + v1.y * zs[4*lane+1]
                    + v1.z * zs[4*lane+2] + v1.w * zs[4*lane+3]
                    + v2.x * zs[128+4*lane+0] + v2.y * zs[128+4*lane+1]
                    + v2.z * zs[128+4*lane+2] + v2.w * zs[128+4*lane+3];
            #pragma unroll
            for (int o = 16; o > 0; o >>= 1) p += __shfl_xor_sync(0xffffffffu, p, o);
            if (lane == 0) lg[asp] = p + lb[asp];
        }
        __syncthreads();

        if (t == 0) {
            float mx = -1e30f;
            #pragma unroll
            for (int aa = 0; aa < NASP; aa++) mx = fmaxf(mx, lg[aa]);
            float s = 0.f;
            #pragma unroll
            for (int aa = 0; aa < NASP; aa++) { float e = expf(lg[aa]-mx); ps[aa] = e; s += e; }
            float inv = 1.f / s;
            #pragma unroll
            for (int aa = 0; aa < NASP; aa++) ps[aa] *= inv;
        }
        __syncthreads();

        {
            float rr = 0.f;
            #pragma unroll
            for (int aa = 0; aa < NASP; aa++) rr += ps[aa] * ((const float*)Tw4)[aa * DD + t];
            float v2 = rr * rr;
            #pragma unroll
            for (int o = 16; o > 0; o >>= 1) v2 += __shfl_xor_sync(0xffffffffu, v2, o);
            if (lane == 0) sh8[wid] = v2;
            __syncthreads();
            float tot = sh8[0]+sh8[1]+sh8[2]+sh8[3]+sh8[4]+sh8[5]+sh8[6]+sh8[7];
            float nrm = fmaxf(sqrtf(tot), 1e-12f);
            out[OFF_RS + b * DD + t] = rr / nrm;
        }
        __syncthreads();
    }
}

extern "C" void kernel_launch(void* const* d_in, const int* in_sizes, int n_in,
                              void* d_out, int out_size)
{
    const int*   pos  = (const int*)d_in[0];
    const int*   negs = (const int*)d_in[1];
    const float* E_w  = (const float*)d_in[2];
    const float* T_w  = (const float*)d_in[3];
    const float* M_w  = (const float*)d_in[4];
    const float* M_b  = (const float*)d_in[5];
    const float* lw   = (const float*)d_in[6];
    const float* lb   = (const float*)d_in[7];
    float* out = (float*)d_out;

    k_all<<<NPOSBLK + NNEGBLK, 256>>>(
        pos, negs, (const float4*)E_w,
        (const float4*)M_w, M_b,
        (const float4*)T_w, (const float4*)lw, lb, out);
}

// round 7
// speedup vs baseline: 1.4836x; 1.1815x over previous
#include <cuda_runtime.h>
#include <math.h>

#define BB    512
#define LL    100
#define MM    10
#define DD    256
#define NASP  14
#define BT    4
#define NPOSBLK (BB/BT)         // 128
#define NNEGBLK (BB*MM)         // 5120

#define OFF_RS  0
#define OFF_ZS  (BB*DD)
#define OFF_ZN  (2*BB*DD)

#define F4ADD(a, v) { a.x += v.x; a.y += v.y; a.z += v.z; a.w += v.w; }

__device__ __forceinline__ void f4fma(float4& a, float s, const float4& v) {
    a.x += s * v.x; a.y += s * v.y; a.z += s * v.z; a.w += s * v.w;
}

// Gather-sum of 25 rows (l = 4*i + r) with 8-deep load batching.
__device__ __forceinline__ float4 gather25(
    const float4* __restrict__ E4, const int* __restrict__ idx,
    int r, int c)
{
    float4 a0 = make_float4(0.f,0.f,0.f,0.f);
    float4 a1 = make_float4(0.f,0.f,0.f,0.f);
    #pragma unroll
    for (int j = 0; j < 3; j++) {
        const int i0 = j * 8;
        float4 v0 = E4[(size_t)idx[(i0+0)*4+r] * 64 + c];
        float4 v1 = E4[(size_t)idx[(i0+1)*4+r] * 64 + c];
        float4 v2 = E4[(size_t)idx[(i0+2)*4+r] * 64 + c];
        float4 v3 = E4[(size_t)idx[(i0+3)*4+r] * 64 + c];
        float4 v4 = E4[(size_t)idx[(i0+4)*4+r] * 64 + c];
        float4 v5 = E4[(size_t)idx[(i0+5)*4+r] * 64 + c];
        float4 v6 = E4[(size_t)idx[(i0+6)*4+r] * 64 + c];
        float4 v7 = E4[(size_t)idx[(i0+7)*4+r] * 64 + c];
        F4ADD(a0, v0); F4ADD(a1, v1); F4ADD(a0, v2); F4ADD(a1, v3);
        F4ADD(a0, v4); F4ADD(a1, v5); F4ADD(a0, v6); F4ADD(a1, v7);
    }
    float4 v = E4[(size_t)idx[24*4+r] * 64 + c];
    F4ADD(a0, v);
    F4ADD(a0, a1);
    return a0;
}

__device__ __forceinline__ float dot8(const float4& v1, const float4& v2,
                                      const float4& m1, const float4& m2)
{
    return v1.x*m1.x + v1.y*m1.y + v1.z*m1.z + v1.w*m1.w
         + v2.x*m2.x + v2.y*m2.y + v2.z*m2.z + v2.w*m2.w;
}

// ---------------------------------------------------------------------------
// Unified kernel, 256 threads/block.
//   blocks [0, NPOSBLK):   full pos chain for BT batches (self-contained)
//   blocks [NPOSBLK, ...): z_n = l2norm(sum_l e)  (mean cancels under l2norm)
// ---------------------------------------------------------------------------
__global__ __launch_bounds__(256, 4) void k_all(
    const int* __restrict__ pos, const int* __restrict__ negs,
    const float4* __restrict__ E4,
    const float4* __restrict__ Mw4, const float* __restrict__ Mb,
    const float4* __restrict__ Tw4, const float4* __restrict__ lw4,
    const float* __restrict__ lb, float* __restrict__ out)
{
    __shared__ float4 redAB[512];   // 8KB; first 256 entries double as the
                                    // phase-reduce buffer
    __shared__ float sh8[8];
    float4* red = redAB;
    const int t = threadIdx.x, blk = blockIdx.x;
    const int r = t >> 6, c = t & 63;
    const int wid = t >> 5, lane = t & 31;

    if (blk >= NPOSBLK) {
        // ---------------- negatives: z_n ----------------
        __shared__ int idx[LL];
        const int bm = blk - NPOSBLK;
        if (t < LL) idx[t] = negs[bm * LL + t];
        __syncthreads();

        float4 a = gather25(E4, idx, r, c);
        red[t] = a;
        __syncthreads();
        if (t < 64) {
            float4 s = red[t], p1 = red[t+64], p2 = red[t+128], p3 = red[t+192];
            s.x += p1.x+p2.x+p3.x; s.y += p1.y+p2.y+p3.y;
            s.z += p1.z+p2.z+p3.z; s.w += p1.w+p2.w+p3.w;
            red[t] = s;
            float ss = s.x*s.x + s.y*s.y + s.z*s.z + s.w*s.w;
            #pragma unroll
            for (int o = 16; o > 0; o >>= 1) ss += __shfl_xor_sync(0xffffffffu, ss, o);
            if (lane == 0) sh8[wid] = ss;
        }
        __syncthreads();
        if (t < 64) {
            float inv = 1.f / fmaxf(sqrtf(sh8[0] + sh8[1]), 1e-12f);
            float4 s = red[t];
            s.x *= inv; s.y *= inv; s.z *= inv; s.w *= inv;
            ((float4*)(out + OFF_ZN))[bm * 64 + t] = s;
        }
        return;
    }

    // ---------------- pos chain for batches [b0, b0+BT) ----------------
    __shared__ int   idxs[BT][LL];
    __shared__ float ysMy[BT][DD];     // ys in phases 1-2, then overlaid by My
    __shared__ float zs[DD];
    __shared__ float lg[NASP];
    __shared__ float ps[NASP];
    const int b0 = blk * BT;

    for (int i = 0; i < BT; i++)
        if (t < LL) idxs[i][t] = pos[(b0 + i) * LL + t];
    __syncthreads();

    // Phase 1: means -> ysMy[i][*]
    for (int i = 0; i < BT; i++) {
        float4 a = gather25(E4, idxs[i], r, c);
        red[t] = a;
        __syncthreads();
        if (t < 64) {
            float4 s = red[t], p1 = red[t+64], p2 = red[t+128], p3 = red[t+192];
            s.x = (s.x+p1.x+p2.x+p3.x) * (1.f/LL);
            s.y = (s.y+p1.y+p2.y+p3.y) * (1.f/LL);
            s.z = (s.z+p1.z+p2.z+p3.z) * (1.f/LL);
            s.w = (s.w+p1.w+p2.w+p3.w) * (1.f/LL);
            ((float4*)ysMy[i])[t] = s;
        }
        __syncthreads();
    }

    // Phase 2: acc[i] = Mw row t . ys[i]; then overlay My into ysMy
    {
        const float4* mr = Mw4 + t * 64;
        float acc[BT];
        #pragma unroll
        for (int i = 0; i < BT; i++) acc[i] = 0.f;
        #pragma unroll 4
        for (int d = 0; d < 64; d++) {
            float4 w = mr[d];
            #pragma unroll
            for (int i = 0; i < BT; i++) {
                acc[i] += w.x * ysMy[i][4*d]   + w.y * ysMy[i][4*d+1]
                        + w.z * ysMy[i][4*d+2] + w.w * ysMy[i][4*d+3];
            }
        }
        float bb = Mb[t];
        __syncthreads();
        #pragma unroll
        for (int i = 0; i < BT; i++) ysMy[i][t] = acc[i] + bb;
    }
    __syncthreads();

    // Phase 3: per-batch FUSED attention (dot + weighted sum in one gather
    // pass; row stays in regs) + aspect head.
    for (int i = 0; i < BT; i++) {
        const int b = b0 + i;
        const float4 m1 = ((const float4*)ysMy[i])[lane];
        const float4 m2 = ((const float4*)ysMy[i])[lane + 32];

        float4 a1 = make_float4(0.f,0.f,0.f,0.f);
        float4 a2 = make_float4(0.f,0.f,0.f,0.f);

        // 2-token software pipeline per warp (tokens l0, l0+8)
        for (int l0 = wid; l0 < LL; l0 += 16) {
            const int l1 = l0 + 8;
            const bool has1 = (l1 < LL);
            const float4* e0 = E4 + (size_t)idxs[i][l0] * 64;
            const float4* e1 = E4 + (size_t)idxs[i][has1 ? l1 : l0] * 64;
            float4 v1 = e0[lane], v2 = e0[lane + 32];
            float4 u1 = e1[lane], u2 = e1[lane + 32];

            float p0 = dot8(v1, v2, m1, m2);
            float p1 = dot8(u1, u2, m1, m2);
            #pragma unroll
            for (int o = 16; o > 0; o >>= 1) {
                p0 += __shfl_xor_sync(0xffffffffu, p0, o);
                p1 += __shfl_xor_sync(0xffffffffu, p1, o);
            }
            float w0 = expf(tanhf(p0));
            float w1 = has1 ? expf(tanhf(p1)) : 0.f;
            f4fma(a1, w0, v1); f4fma(a2, w0, v2);
            f4fma(a1, w1, u1); f4fma(a2, w1, u2);
        }

        // cross-warp reduce: warp wid holds float4-cols lane (a1), 32+lane (a2)
        redAB[wid * 32 + lane] = a1;           // [0..255]
        redAB[256 + wid * 32 + lane] = a2;     // [256..511]
        __syncthreads();
        if (t < 64) {
            const int base = (t < 32) ? t : (256 + t - 32);
            float4 s = redAB[base];
            #pragma unroll
            for (int w = 1; w < 8; w++) {
                float4 p = redAB[base + w * 32];
                F4ADD(s, p);
            }
            red[t] = s;
            float ss = s.x*s.x + s.y*s.y + s.z*s.z + s.w*s.w;
            #pragma unroll
            for (int o = 16; o > 0; o >>= 1) ss += __shfl_xor_sync(0xffffffffu, ss, o);
            if (lane == 0) sh8[wid] = ss;
        }
        __syncthreads();
        if (t < 64) {
            float inv = 1.f / fmaxf(sqrtf(sh8[0] + sh8[1]), 1e-12f);
            float4 s = red[t];
            s.x *= inv; s.y *= inv; s.z *= inv; s.w *= inv;
            ((float4*)zs)[t] = s;
            ((float4*)(out + OFF_ZS))[b * 64 + t] = s;
        }
        __syncthreads();

        // logits over 14 aspects (warp per aspect)
        for (int asp = wid; asp < NASP; asp += 8) {
            const float4* lr = lw4 + asp * 64;
            float4 v1 = lr[lane], v2 = lr[lane + 32];
            float4 z1 = ((const float4*)zs)[lane];
            float4 z2 = ((const float4*)zs)[lane + 32];
            float p = dot8(v1, v2, z1, z2);
            #pragma unroll
            for (int o = 16; o > 0; o >>= 1) p += __shfl_xor_sync(0xffffffffu, p, o);
            if (lane == 0) lg[asp] = p + lb[asp];
        }
        __syncthreads();

        if (t == 0) {
            float mx = -1e30f;
            #pragma unroll
            for (int aa = 0; aa < NASP; aa++) mx = fmaxf(mx, lg[aa]);
            float s = 0.f;
            #pragma unroll
            for (int aa = 0; aa < NASP; aa++) { float e = expf(lg[aa]-mx); ps[aa] = e; s += e; }
            float inv = 1.f / s;
            #pragma unroll
            for (int aa = 0; aa < NASP; aa++) ps[aa] *= inv;
        }
        __syncthreads();

        {
            float rr = 0.f;
            #pragma unroll
            for (int aa = 0; aa < NASP; aa++) rr += ps[aa] * ((const float*)Tw4)[aa * DD + t];
            float v2 = rr * rr;
            #pragma unroll
            for (int o = 16; o > 0; o >>= 1) v2 += __shfl_xor_sync(0xffffffffu, v2, o);
            if (lane == 0) sh8[wid] = v2;
            __syncthreads();
            float tot = sh8[0]+sh8[1]+sh8[2]+sh8[3]+sh8[4]+sh8[5]+sh8[6]+sh8[7];
            float nrm = fmaxf(sqrtf(tot), 1e-12f);
            out[OFF_RS + b * DD + t] = rr / nrm;
        }
        __syncthreads();
    }
}

extern "C" void kernel_launch(void* const* d_in, const int* in_sizes, int n_in,
                              void* d_out, int out_size)
{
    const int*   pos  = (const int*)d_in[0];
    const int*   negs = (const int*)d_in[1];
    const float* E_w  = (const float*)d_in[2];
    const float* T_w  = (const float*)d_in[3];
    const float* M_w  = (const float*)d_in[4];
    const float* M_b  = (const float*)d_in[5];
    const float* lw   = (const float*)d_in[6];
    const float* lb   = (const float*)d_in[7];
    float* out = (float*)d_out;

    k_all<<<NPOSBLK + NNEGBLK, 256>>>(
        pos, negs, (const float4*)E_w,
        (const float4*)M_w, M_b,
        (const float4*)T_w, (const float4*)lw, lb, out);
}